// round 3
// baseline (speedup 1.0000x reference)
#include <cuda_runtime.h>
#include <cuda_fp16.h>
#include <cstdint>
#include <cstddef>

// ============================================================================
// BitLinear: out = (x_q @ w_q) * (beta * gamma_row)
//   x: [32768, 1024] f32, w: [1024, 1024] f32, out: [32768, 1024] f32
//   a = mean(w); w_q = sign(w - a); gamma = rowmax|x|;
//   x_q = clip(x/(gamma+eps), -1+eps, 1-eps); scale = beta*gamma; beta = max|w|
//
// Target is base sm_100 (no 'a'/'f' suffix -> NO tcgen05/TMEM). Use the
// family-agnostic tensor path: cp.async + ldmatrix + mma.sync (m16n8k16 f16,
// fp32 accum). fp16 quantized operands keep rel_err ~3e-4.
// ============================================================================

#define EPSV 1e-5f

static constexpr int N_ROWS  = 32768;
static constexpr int K_DIM   = 1024;
static constexpr int OUT_DIM = 1024;

// ---------------- device scratch (static, allocation-free) -----------------
__device__ __align__(1024) __half g_xq[(size_t)N_ROWS * K_DIM];   // 64 MB
__device__ __align__(1024) __half g_wqT[(size_t)OUT_DIM * K_DIM]; // 2 MB, [n][k]
__device__ float g_scale[N_ROWS];
__device__ float g_psum[1024];
__device__ float g_pmax[1024];
__device__ float g_mean_beta[2];  // [0]=mean a, [1]=beta

// ============================= asm helpers ==================================
__device__ __forceinline__ uint32_t smem_u32(const void* p) {
    return (uint32_t)__cvta_generic_to_shared(p);
}

#define CP_ASYNC16(dst_u32, src_ptr) \
    asm volatile("cp.async.cg.shared.global [%0], [%1], 16;" \
        :: "r"(dst_u32), "l"(src_ptr) : "memory")
#define CP_COMMIT() asm volatile("cp.async.commit_group;" ::: "memory")
#define CP_WAIT(n)  asm volatile("cp.async.wait_group %0;" :: "n"(n) : "memory")

#define SWZ(off) ((off) ^ (((off) >> 3) & 0x70))

__device__ __forceinline__ void ldsm_x4(uint32_t r[4], uint32_t addr) {
    asm volatile("ldmatrix.sync.aligned.m8n8.x4.shared.b16 {%0,%1,%2,%3}, [%4];"
        : "=r"(r[0]), "=r"(r[1]), "=r"(r[2]), "=r"(r[3]) : "r"(addr));
}

__device__ __forceinline__ void mma16816(float c[4], const uint32_t a[4],
                                         uint32_t b0, uint32_t b1) {
    asm volatile(
        "mma.sync.aligned.m16n8k16.row.col.f32.f16.f16.f32 "
        "{%0,%1,%2,%3}, {%4,%5,%6,%7}, {%8,%9}, {%0,%1,%2,%3};"
        : "+f"(c[0]), "+f"(c[1]), "+f"(c[2]), "+f"(c[3])
        : "r"(a[0]), "r"(a[1]), "r"(a[2]), "r"(a[3]), "r"(b0), "r"(b1));
}

// ======================= kernel 1: weight stats partials ====================
__global__ void stats1_kernel(const float4* __restrict__ w) {
    __shared__ float ssum[256];
    __shared__ float smax[256];
    int t = threadIdx.x;
    float4 v = w[(size_t)blockIdx.x * 256 + t];
    ssum[t] = v.x + v.y + v.z + v.w;
    smax[t] = fmaxf(fmaxf(fabsf(v.x), fabsf(v.y)), fmaxf(fabsf(v.z), fabsf(v.w)));
    __syncthreads();
    for (int off = 128; off > 0; off >>= 1) {
        if (t < off) {
            ssum[t] += ssum[t + off];
            smax[t] = fmaxf(smax[t], smax[t + off]);
        }
        __syncthreads();
    }
    if (t == 0) {
        g_psum[blockIdx.x] = ssum[0];
        g_pmax[blockIdx.x] = smax[0];
    }
}

// ======================= kernel 2: finalize mean / beta =====================
__global__ void stats2_kernel() {
    __shared__ float ssum[256];
    __shared__ float smax[256];
    int t = threadIdx.x;
    float s = 0.f, m = 0.f;
    for (int i = t; i < 1024; i += 256) {
        s += g_psum[i];
        m = fmaxf(m, g_pmax[i]);
    }
    ssum[t] = s; smax[t] = m;
    __syncthreads();
    for (int off = 128; off > 0; off >>= 1) {
        if (t < off) {
            ssum[t] += ssum[t + off];
            smax[t] = fmaxf(smax[t], smax[t + off]);
        }
        __syncthreads();
    }
    if (t == 0) {
        g_mean_beta[0] = ssum[0] * (1.0f / 1048576.0f);
        g_mean_beta[1] = smax[0];
    }
}

// ============ kernel 3: transpose + sign-quantize weight -> wqT[n][k] =======
__global__ void wquant_kernel(const float* __restrict__ w) {
    __shared__ float tile[32][33];
    int n0 = blockIdx.x * 32, k0 = blockIdx.y * 32;
    int tx = threadIdx.x, ty = threadIdx.y;
    #pragma unroll
    for (int i = 0; i < 32; i += 8)
        tile[ty + i][tx] = w[(size_t)(k0 + ty + i) * OUT_DIM + n0 + tx];
    __syncthreads();
    float a = g_mean_beta[0];
    #pragma unroll
    for (int i = 0; i < 32; i += 8) {
        float v = tile[tx][ty + i];                 // = w[k0+tx][n0+ty+i]
        float sgn = (v > a) ? 1.0f : ((v < a) ? -1.0f : 0.0f);
        g_wqT[(size_t)(n0 + ty + i) * K_DIM + k0 + tx] = __float2half(sgn);
    }
}

// ============ kernel 4: per-row gamma + fp16 quantize x + row scale =========
__global__ void xquant_kernel(const float4* __restrict__ x) {
    int row = blockIdx.x;
    int t = threadIdx.x;  // 128 threads, 8 floats each
    const float4* xr = x + (size_t)row * 256;
    float4 v0 = xr[t * 2 + 0];
    float4 v1 = xr[t * 2 + 1];
    float m = fmaxf(
        fmaxf(fmaxf(fabsf(v0.x), fabsf(v0.y)), fmaxf(fabsf(v0.z), fabsf(v0.w))),
        fmaxf(fmaxf(fabsf(v1.x), fabsf(v1.y)), fmaxf(fabsf(v1.z), fabsf(v1.w))));
    #pragma unroll
    for (int off = 16; off > 0; off >>= 1)
        m = fmaxf(m, __shfl_xor_sync(0xFFFFFFFFu, m, off));
    __shared__ float wm[4];
    if ((t & 31) == 0) wm[t >> 5] = m;
    __syncthreads();
    float gamma = fmaxf(fmaxf(wm[0], wm[1]), fmaxf(wm[2], wm[3]));
    float inv = 1.0f / (gamma + EPSV);
    if (t == 0) g_scale[row] = g_mean_beta[1] * gamma;

    const float lo = -1.0f + EPSV, hi = 1.0f - EPSV;
    float q[8] = {v0.x, v0.y, v0.z, v0.w, v1.x, v1.y, v1.z, v1.w};
    uint32_t u[4];
    #pragma unroll
    for (int i = 0; i < 4; ++i) {
        float a0 = fminf(fmaxf(q[2 * i + 0] * inv, lo), hi);
        float a1 = fminf(fmaxf(q[2 * i + 1] * inv, lo), hi);
        __half2 h = __floats2half2_rn(a0, a1);
        u[i] = *reinterpret_cast<uint32_t*>(&h);
    }
    reinterpret_cast<uint4*>(g_xq)[(size_t)row * 128 + t] = make_uint4(u[0], u[1], u[2], u[3]);
}

// =========================== kernel 5: GEMM =================================
// CTA tile 128x128x64, 4-stage cp.async pipeline, 8 warps (2x4) of 64x32.
static constexpr int M_TILE = 128;
static constexpr int N_TILE = 128;
static constexpr int K_TILE = 64;                  // 128 B per row fp16
static constexpr int STAGES = 4;
static constexpr int K_ITERS = K_DIM / K_TILE;     // 16

static constexpr uint32_t A_BYTES   = M_TILE * 128;        // 16 KB
static constexpr uint32_t B_BYTES   = N_TILE * 128;        // 16 KB
static constexpr uint32_t STG_BYTES = A_BYTES + B_BYTES;   // 32 KB
static constexpr uint32_t SMEM_TOTAL = STAGES * STG_BYTES; // 128 KB

__device__ __forceinline__ void issue_stage(
    uint32_t sbase, int s, int kt, int m_base, int n_base,
    const __half* __restrict__ A, const __half* __restrict__ B, int t)
{
    uint32_t a_s = sbase + s * STG_BYTES;
    uint32_t b_s = a_s + A_BYTES;
    // A: 128 rows x 8 chunks of 16B = 1024 chunks; 256 threads x 4
    #pragma unroll
    for (int i = 0; i < 4; ++i) {
        int idx = t + i * 256;
        int row = idx >> 3, chk = idx & 7;
        uint32_t off = (uint32_t)(row * 128 + chk * 16);
        const __half* src = A + (size_t)(m_base + row) * K_DIM + kt * K_TILE + chk * 8;
        CP_ASYNC16(a_s + SWZ(off), src);
    }
    #pragma unroll
    for (int i = 0; i < 4; ++i) {
        int idx = t + i * 256;
        int row = idx >> 3, chk = idx & 7;
        uint32_t off = (uint32_t)(row * 128 + chk * 16);
        const __half* src = B + (size_t)(n_base + row) * K_DIM + kt * K_TILE + chk * 8;
        CP_ASYNC16(b_s + SWZ(off), src);
    }
    CP_COMMIT();
}

__global__ void __launch_bounds__(256) gemm_kernel(
    const __half* __restrict__ A,   // g_xq   [N_ROWS][K]
    const __half* __restrict__ B,   // g_wqT  [OUT][K]
    const float* __restrict__ scale,
    float* __restrict__ out)
{
    extern __shared__ char smem[];
    uint32_t sb = smem_u32(smem);
    int t = threadIdx.x, lane = t & 31, wid = t >> 5;
    int warp_m = wid & 1, warp_n = wid >> 1;        // 2 x 4 warps

    int m_base = blockIdx.y * M_TILE;
    int n_base = blockIdx.x * N_TILE;

    float acc[4][4][4];
    #pragma unroll
    for (int i = 0; i < 4; ++i)
        #pragma unroll
        for (int j = 0; j < 4; ++j)
            #pragma unroll
            for (int v = 0; v < 4; ++v) acc[i][j][v] = 0.f;

    // prologue: fill STAGES-1 stages
    #pragma unroll
    for (int s = 0; s < STAGES - 1; ++s)
        issue_stage(sb, s, s, m_base, n_base, A, B, t);

    // ldmatrix lane address components (same pattern for A and B):
    // row = lane%16 within tile, 16B column-block = lane/16
    int lrow = lane & 15;
    int lcb  = (lane >> 4) * 16;

    #pragma unroll 1
    for (int it = 0; it < K_ITERS; ++it) {
        CP_WAIT(2);
        __syncthreads();
        if (it + STAGES - 1 < K_ITERS)
            issue_stage(sb, (it + STAGES - 1) & (STAGES - 1), it + STAGES - 1,
                        m_base, n_base, A, B, t);

        int s = it & (STAGES - 1);
        uint32_t a_s = sb + s * STG_BYTES;
        uint32_t b_s = a_s + A_BYTES;

        #pragma unroll
        for (int ks = 0; ks < 4; ++ks) {
            int colb = ks * 32 + lcb;
            uint32_t af[4][4];
            #pragma unroll
            for (int mi = 0; mi < 4; ++mi) {
                uint32_t off = (uint32_t)((warp_m * 64 + mi * 16 + lrow) * 128 + colb);
                ldsm_x4(af[mi], a_s + SWZ(off));
            }
            uint32_t bf[2][4];
            #pragma unroll
            for (int nj = 0; nj < 2; ++nj) {
                uint32_t off = (uint32_t)((warp_n * 32 + nj * 16 + lrow) * 128 + colb);
                ldsm_x4(bf[nj], b_s + SWZ(off));
            }
            #pragma unroll
            for (int mi = 0; mi < 4; ++mi)
                #pragma unroll
                for (int nb = 0; nb < 4; ++nb)
                    mma16816(acc[mi][nb], af[mi],
                             bf[nb >> 1][nb & 1], bf[nb >> 1][(nb & 1) + 2]);
        }
    }

    // epilogue: scale rows and store
    #pragma unroll
    for (int mi = 0; mi < 4; ++mi) {
        int r0 = m_base + warp_m * 64 + mi * 16 + (lane >> 2);
        float sc0 = scale[r0];
        float sc1 = scale[r0 + 8];
        float* o0 = out + (size_t)r0 * OUT_DIM + n_base + warp_n * 32 + (lane & 3) * 2;
        float* o1 = o0 + 8 * OUT_DIM;
        #pragma unroll
        for (int nb = 0; nb < 4; ++nb) {
            float2 v0 = make_float2(acc[mi][nb][0] * sc0, acc[mi][nb][1] * sc0);
            float2 v1 = make_float2(acc[mi][nb][2] * sc1, acc[mi][nb][3] * sc1);
            *reinterpret_cast<float2*>(o0 + nb * 8) = v0;
            *reinterpret_cast<float2*>(o1 + nb * 8) = v1;
        }
    }
}

// ============================== host launch =================================
extern "C" void kernel_launch(void* const* d_in, const int* in_sizes, int n_in,
                              void* d_out, int out_size) {
    const float* x;
    const float* w;
    if (in_sizes[0] == OUT_DIM * K_DIM) {  // weight first
        w = (const float*)d_in[0];
        x = (const float*)d_in[1];
    } else {
        x = (const float*)d_in[0];
        w = (const float*)d_in[1];
    }

    void* xq_ptr = nullptr;
    void* wq_ptr = nullptr;
    void* sc_ptr = nullptr;
    cudaGetSymbolAddress(&xq_ptr, g_xq);
    cudaGetSymbolAddress(&wq_ptr, g_wqT);
    cudaGetSymbolAddress(&sc_ptr, g_scale);

    cudaFuncSetAttribute(gemm_kernel, cudaFuncAttributeMaxDynamicSharedMemorySize,
                         (int)SMEM_TOTAL);

    stats1_kernel<<<1024, 256>>>((const float4*)w);
    stats2_kernel<<<1, 256>>>();
    wquant_kernel<<<dim3(OUT_DIM / 32, K_DIM / 32), dim3(32, 8)>>>(w);
    xquant_kernel<<<N_ROWS, 128>>>((const float4*)x);
    gemm_kernel<<<dim3(OUT_DIM / N_TILE, N_ROWS / M_TILE), 256, SMEM_TOTAL>>>(
        (const __half*)xq_ptr, (const __half*)wq_ptr, (const float*)sc_ptr,
        (float*)d_out);
}

// round 6
// speedup vs baseline: 1.2015x; 1.2015x over previous
#include <cuda_runtime.h>
#include <cuda_fp16.h>
#include <cstdint>
#include <cstddef>

// ============================================================================
// BitLinear: out = (x_q @ w_q) * (beta * gamma_row)
// R6 = R4/R5 resubmit (broker infra failures): GEMM occupancy 1 -> 2 CTAs/SM
// (STAGES 4->3, 96KB smem, launch_bounds(256,2))
// ============================================================================

#define EPSV 1e-5f

static constexpr int N_ROWS  = 32768;
static constexpr int K_DIM   = 1024;
static constexpr int OUT_DIM = 1024;

// ---------------- device scratch (static, allocation-free) -----------------
__device__ __align__(1024) __half g_xq[(size_t)N_ROWS * K_DIM];   // 64 MB
__device__ __align__(1024) __half g_wqT[(size_t)OUT_DIM * K_DIM]; // 2 MB, [n][k]
__device__ float g_scale[N_ROWS];
__device__ float g_psum[1024];
__device__ float g_pmax[1024];
__device__ float g_mean_beta[2];  // [0]=mean a, [1]=beta

// ============================= asm helpers ==================================
__device__ __forceinline__ uint32_t smem_u32(const void* p) {
    return (uint32_t)__cvta_generic_to_shared(p);
}

#define CP_ASYNC16(dst_u32, src_ptr) \
    asm volatile("cp.async.cg.shared.global [%0], [%1], 16;" \
        :: "r"(dst_u32), "l"(src_ptr) : "memory")
#define CP_COMMIT() asm volatile("cp.async.commit_group;" ::: "memory")
#define CP_WAIT(n)  asm volatile("cp.async.wait_group %0;" :: "n"(n) : "memory")

#define SWZ(off) ((off) ^ (((off) >> 3) & 0x70))

__device__ __forceinline__ void ldsm_x4(uint32_t r[4], uint32_t addr) {
    asm volatile("ldmatrix.sync.aligned.m8n8.x4.shared.b16 {%0,%1,%2,%3}, [%4];"
        : "=r"(r[0]), "=r"(r[1]), "=r"(r[2]), "=r"(r[3]) : "r"(addr));
}

__device__ __forceinline__ void mma16816(float c[4], const uint32_t a[4],
                                         uint32_t b0, uint32_t b1) {
    asm volatile(
        "mma.sync.aligned.m16n8k16.row.col.f32.f16.f16.f32 "
        "{%0,%1,%2,%3}, {%4,%5,%6,%7}, {%8,%9}, {%0,%1,%2,%3};"
        : "+f"(c[0]), "+f"(c[1]), "+f"(c[2]), "+f"(c[3])
        : "r"(a[0]), "r"(a[1]), "r"(a[2]), "r"(a[3]), "r"(b0), "r"(b1));
}

// ======================= kernel 1: weight stats partials ====================
__global__ void stats1_kernel(const float4* __restrict__ w) {
    __shared__ float ssum[256];
    __shared__ float smax[256];
    int t = threadIdx.x;
    float4 v = w[(size_t)blockIdx.x * 256 + t];
    ssum[t] = v.x + v.y + v.z + v.w;
    smax[t] = fmaxf(fmaxf(fabsf(v.x), fabsf(v.y)), fmaxf(fabsf(v.z), fabsf(v.w)));
    __syncthreads();
    for (int off = 128; off > 0; off >>= 1) {
        if (t < off) {
            ssum[t] += ssum[t + off];
            smax[t] = fmaxf(smax[t], smax[t + off]);
        }
        __syncthreads();
    }
    if (t == 0) {
        g_psum[blockIdx.x] = ssum[0];
        g_pmax[blockIdx.x] = smax[0];
    }
}

// ======================= kernel 2: finalize mean / beta =====================
__global__ void stats2_kernel() {
    __shared__ float ssum[256];
    __shared__ float smax[256];
    int t = threadIdx.x;
    float s = 0.f, m = 0.f;
    for (int i = t; i < 1024; i += 256) {
        s += g_psum[i];
        m = fmaxf(m, g_pmax[i]);
    }
    ssum[t] = s; smax[t] = m;
    __syncthreads();
    for (int off = 128; off > 0; off >>= 1) {
        if (t < off) {
            ssum[t] += ssum[t + off];
            smax[t] = fmaxf(smax[t], smax[t + off]);
        }
        __syncthreads();
    }
    if (t == 0) {
        g_mean_beta[0] = ssum[0] * (1.0f / 1048576.0f);
        g_mean_beta[1] = smax[0];
    }
}

// ============ kernel 3: transpose + sign-quantize weight -> wqT[n][k] =======
__global__ void wquant_kernel(const float* __restrict__ w) {
    __shared__ float tile[32][33];
    int n0 = blockIdx.x * 32, k0 = blockIdx.y * 32;
    int tx = threadIdx.x, ty = threadIdx.y;
    #pragma unroll
    for (int i = 0; i < 32; i += 8)
        tile[ty + i][tx] = w[(size_t)(k0 + ty + i) * OUT_DIM + n0 + tx];
    __syncthreads();
    float a = g_mean_beta[0];
    #pragma unroll
    for (int i = 0; i < 32; i += 8) {
        float v = tile[tx][ty + i];                 // = w[k0+tx][n0+ty+i]
        float sgn = (v > a) ? 1.0f : ((v < a) ? -1.0f : 0.0f);
        g_wqT[(size_t)(n0 + ty + i) * K_DIM + k0 + tx] = __float2half(sgn);
    }
}

// ============ kernel 4: per-row gamma + fp16 quantize x + row scale =========
__global__ void xquant_kernel(const float4* __restrict__ x) {
    int row = blockIdx.x;
    int t = threadIdx.x;  // 128 threads, 8 floats each
    const float4* xr = x + (size_t)row * 256;
    float4 v0 = xr[t * 2 + 0];
    float4 v1 = xr[t * 2 + 1];
    float m = fmaxf(
        fmaxf(fmaxf(fabsf(v0.x), fabsf(v0.y)), fmaxf(fabsf(v0.z), fabsf(v0.w))),
        fmaxf(fmaxf(fabsf(v1.x), fabsf(v1.y)), fmaxf(fabsf(v1.z), fabsf(v1.w))));
    #pragma unroll
    for (int off = 16; off > 0; off >>= 1)
        m = fmaxf(m, __shfl_xor_sync(0xFFFFFFFFu, m, off));
    __shared__ float wm[4];
    if ((t & 31) == 0) wm[t >> 5] = m;
    __syncthreads();
    float gamma = fmaxf(fmaxf(wm[0], wm[1]), fmaxf(wm[2], wm[3]));
    float inv = 1.0f / (gamma + EPSV);
    if (t == 0) g_scale[row] = g_mean_beta[1] * gamma;

    const float lo = -1.0f + EPSV, hi = 1.0f - EPSV;
    float q[8] = {v0.x, v0.y, v0.z, v0.w, v1.x, v1.y, v1.z, v1.w};
    uint32_t u[4];
    #pragma unroll
    for (int i = 0; i < 4; ++i) {
        float a0 = fminf(fmaxf(q[2 * i + 0] * inv, lo), hi);
        float a1 = fminf(fmaxf(q[2 * i + 1] * inv, lo), hi);
        __half2 h = __floats2half2_rn(a0, a1);
        u[i] = *reinterpret_cast<uint32_t*>(&h);
    }
    reinterpret_cast<uint4*>(g_xq)[(size_t)row * 128 + t] = make_uint4(u[0], u[1], u[2], u[3]);
}

// =========================== kernel 5: GEMM =================================
// CTA tile 128x128x64, 3-stage cp.async pipeline, 8 warps (2x4) of 64x32.
// 96 KB smem -> 2 CTAs/SM (16 warps/SM) for latency hiding.
static constexpr int M_TILE = 128;
static constexpr int N_TILE = 128;
static constexpr int K_TILE = 64;                  // 128 B per row fp16
static constexpr int STAGES = 3;
static constexpr int K_ITERS = K_DIM / K_TILE;     // 16

static constexpr uint32_t A_BYTES   = M_TILE * 128;        // 16 KB
static constexpr uint32_t B_BYTES   = N_TILE * 128;        // 16 KB
static constexpr uint32_t STG_BYTES = A_BYTES + B_BYTES;   // 32 KB
static constexpr uint32_t SMEM_TOTAL = STAGES * STG_BYTES; // 96 KB

__device__ __forceinline__ void issue_stage(
    uint32_t sbase, int s, int kt, int m_base, int n_base,
    const __half* __restrict__ A, const __half* __restrict__ B, int t)
{
    uint32_t a_s = sbase + s * STG_BYTES;
    uint32_t b_s = a_s + A_BYTES;
    // A: 128 rows x 8 chunks of 16B = 1024 chunks; 256 threads x 4
    #pragma unroll
    for (int i = 0; i < 4; ++i) {
        int idx = t + i * 256;
        int row = idx >> 3, chk = idx & 7;
        uint32_t off = (uint32_t)(row * 128 + chk * 16);
        const __half* src = A + (size_t)(m_base + row) * K_DIM + kt * K_TILE + chk * 8;
        CP_ASYNC16(a_s + SWZ(off), src);
    }
    #pragma unroll
    for (int i = 0; i < 4; ++i) {
        int idx = t + i * 256;
        int row = idx >> 3, chk = idx & 7;
        uint32_t off = (uint32_t)(row * 128 + chk * 16);
        const __half* src = B + (size_t)(n_base + row) * K_DIM + kt * K_TILE + chk * 8;
        CP_ASYNC16(b_s + SWZ(off), src);
    }
    CP_COMMIT();
}

__global__ void __launch_bounds__(256, 2) gemm_kernel(
    const __half* __restrict__ A,   // g_xq   [N_ROWS][K]
    const __half* __restrict__ B,   // g_wqT  [OUT][K]
    const float* __restrict__ scale,
    float* __restrict__ out)
{
    extern __shared__ char smem[];
    uint32_t sb = smem_u32(smem);
    int t = threadIdx.x, lane = t & 31, wid = t >> 5;
    int warp_m = wid & 1, warp_n = wid >> 1;        // 2 x 4 warps

    int m_base = blockIdx.y * M_TILE;
    int n_base = blockIdx.x * N_TILE;

    float acc[4][4][4];
    #pragma unroll
    for (int i = 0; i < 4; ++i)
        #pragma unroll
        for (int j = 0; j < 4; ++j)
            #pragma unroll
            for (int v = 0; v < 4; ++v) acc[i][j][v] = 0.f;

    // prologue: fill STAGES-1 stages
    #pragma unroll
    for (int s = 0; s < STAGES - 1; ++s)
        issue_stage(sb, s, s, m_base, n_base, A, B, t);

    // ldmatrix lane address components (same pattern for A and B):
    // row = lane%16 within tile, 16B column-block = lane/16
    int lrow = lane & 15;
    int lcb  = (lane >> 4) * 16;

    int s_cur = 0;      // stage holding K-iter 'it'
    int s_fill = STAGES - 1;

    #pragma unroll 1
    for (int it = 0; it < K_ITERS; ++it) {
        CP_WAIT(STAGES - 2);
        __syncthreads();
        if (it + STAGES - 1 < K_ITERS)
            issue_stage(sb, s_fill, it + STAGES - 1, m_base, n_base, A, B, t);

        uint32_t a_s = sb + s_cur * STG_BYTES;
        uint32_t b_s = a_s + A_BYTES;

        #pragma unroll
        for (int ks = 0; ks < 4; ++ks) {
            int colb = ks * 32 + lcb;
            uint32_t af[4][4];
            #pragma unroll
            for (int mi = 0; mi < 4; ++mi) {
                uint32_t off = (uint32_t)((warp_m * 64 + mi * 16 + lrow) * 128 + colb);
                ldsm_x4(af[mi], a_s + SWZ(off));
            }
            uint32_t bf[2][4];
            #pragma unroll
            for (int nj = 0; nj < 2; ++nj) {
                uint32_t off = (uint32_t)((warp_n * 32 + nj * 16 + lrow) * 128 + colb);
                ldsm_x4(bf[nj], b_s + SWZ(off));
            }
            #pragma unroll
            for (int mi = 0; mi < 4; ++mi)
                #pragma unroll
                for (int nb = 0; nb < 4; ++nb)
                    mma16816(acc[mi][nb], af[mi],
                             bf[nb >> 1][nb & 1], bf[nb >> 1][(nb & 1) + 2]);
        }

        s_cur = (s_cur == STAGES - 1) ? 0 : s_cur + 1;
        s_fill = (s_fill == STAGES - 1) ? 0 : s_fill + 1;
    }

    // epilogue: scale rows and store
    #pragma unroll
    for (int mi = 0; mi < 4; ++mi) {
        int r0 = m_base + warp_m * 64 + mi * 16 + (lane >> 2);
        float sc0 = scale[r0];
        float sc1 = scale[r0 + 8];
        float* o0 = out + (size_t)r0 * OUT_DIM + n_base + warp_n * 32 + (lane & 3) * 2;
        float* o1 = o0 + 8 * OUT_DIM;
        #pragma unroll
        for (int nb = 0; nb < 4; ++nb) {
            float2 v0 = make_float2(acc[mi][nb][0] * sc0, acc[mi][nb][1] * sc0);
            float2 v1 = make_float2(acc[mi][nb][2] * sc1, acc[mi][nb][3] * sc1);
            *reinterpret_cast<float2*>(o0 + nb * 8) = v0;
            *reinterpret_cast<float2*>(o1 + nb * 8) = v1;
        }
    }
}

// ============================== host launch =================================
extern "C" void kernel_launch(void* const* d_in, const int* in_sizes, int n_in,
                              void* d_out, int out_size) {
    const float* x;
    const float* w;
    if (in_sizes[0] == OUT_DIM * K_DIM) {  // weight first
        w = (const float*)d_in[0];
        x = (const float*)d_in[1];
    } else {
        x = (const float*)d_in[0];
        w = (const float*)d_in[1];
    }

    void* xq_ptr = nullptr;
    void* wq_ptr = nullptr;
    void* sc_ptr = nullptr;
    cudaGetSymbolAddress(&xq_ptr, g_xq);
    cudaGetSymbolAddress(&wq_ptr, g_wqT);
    cudaGetSymbolAddress(&sc_ptr, g_scale);

    cudaFuncSetAttribute(gemm_kernel, cudaFuncAttributeMaxDynamicSharedMemorySize,
                         (int)SMEM_TOTAL);

    stats1_kernel<<<1024, 256>>>((const float4*)w);
    stats2_kernel<<<1, 256>>>();
    wquant_kernel<<<dim3(OUT_DIM / 32, K_DIM / 32), dim3(32, 8)>>>(w);
    xquant_kernel<<<N_ROWS, 128>>>((const float4*)x);
    gemm_kernel<<<dim3(OUT_DIM / N_TILE, N_ROWS / M_TILE), 256, SMEM_TOTAL>>>(
        (const __half*)xq_ptr, (const __half*)wq_ptr, (const float*)sc_ptr,
        (float*)d_out);
}